// round 8
// baseline (speedup 1.0000x reference)
#include <cuda_runtime.h>
#include <math.h>

// ---------------------------------------------------------------------------
// PathGuidedAggregator: S=8192 x P=16 x K=16, D=128, H=64
// Round 6: R5 minus the sPart overlap bug. Phase-B tile dq8/j4/p4 with
// VECTORIZED float4 agg loads (32 LDS/thread; R3=48, R4=80). Stores revert
// to R4's known-good PART_PSTRIDE=33 scalar ull layout (33 >= 32 required;
// R5's 20 overlapped path rows -> corruption).
// ---------------------------------------------------------------------------

#define DD 128
#define PP 16
#define KK 16
#define HH 64
#define AGG_STRIDE 132           // floats per sAgg row
#define PART_PSTRIDE 33          // ull per path row in sPart (must be >= 32)
#define PART_DQ (16 * PART_PSTRIDE)  // 528 ull per d-group bank

__device__ int g_mask_mode; // 0 = uint8, 1 = int32, 2 = float32

__global__ void detect_mask_kernel(const unsigned int* __restrict__ w) {
    __shared__ int f_gt1, f_one;
    if (threadIdx.x == 0) { f_gt1 = 0; f_one = 0; }
    __syncthreads();
    unsigned v = w[threadIdx.x];
    if (v == 0x3F800000u)      atomicOr(&f_one, 1);
    else if (v > 1u)           atomicOr(&f_gt1, 1);
    __syncthreads();
    if (threadIdx.x == 0)
        g_mask_mode = f_gt1 ? 0 : (f_one ? 2 : 1);
}

// ---- packed f32x2 helpers (sm_100+) ---------------------------------------
__device__ __forceinline__ unsigned long long pack2(float x, float y) {
    unsigned long long r;
    asm("mov.b64 %0, {%1, %2};" : "=l"(r) : "f"(x), "f"(y));
    return r;
}
__device__ __forceinline__ float2 unpack2(unsigned long long v) {
    float2 r;
    asm("mov.b64 {%0, %1}, %2;" : "=f"(r.x), "=f"(r.y) : "l"(v));
    return r;
}
__device__ __forceinline__ void fma2(unsigned long long& acc,
                                     unsigned long long a,
                                     unsigned long long b) {
    asm("fma.rn.f32x2 %0, %1, %2, %0;" : "+l"(acc) : "l"(a), "l"(b));
}

// Dynamic SMEM layout (float index):
//   sW1   [0     .. 8192)    32 KB   W1[d][j] row-major
//   sAgg  [8192  .. 10304)   16 x 132 floats
//   sPart [10304 .. 18752)   8 dq x 528 ull (33.8 KB)
//   sWgt  [18752 .. 18768)
//   sVal  [18768 .. 18784)  (int)
static const int SMEM_FLOATS = 18784;

__global__ void __launch_bounds__(512, 3)
pga_kernel(const float* __restrict__ E, const float* __restrict__ W1,
           const float* __restrict__ b1, const float* __restrict__ W2,
           const float* __restrict__ b2, const int* __restrict__ sids,
           const int* __restrict__ eids, const void* __restrict__ maskp,
           float* __restrict__ out, int S) {
    extern __shared__ float smem[];
    float* sW1  = smem;
    float* sAgg = smem + 8192;
    unsigned long long* sPart = (unsigned long long*)(smem + 10304);
    float* sWgt = smem + 18752;
    int*   sVal = (int*)(smem + 18768);

    const int t = threadIdx.x;
    const int lane = t & 31;
    const int warp = t >> 5;

    // W1 -> smem (vectorized)
    {
        const float4* w4 = (const float4*)W1;
        #pragma unroll
        for (int i = t; i < DD * HH / 4; i += 512)
            ((float4*)sW1)[i] = __ldg(w4 + i);
    }
    // Phase C per-thread constants (indexed by lane only)
    const float rb1x = __ldg(b1 + 2 * lane);
    const float rb1y = __ldg(b1 + 2 * lane + 1);
    const float rw2x = __ldg(W2 + 2 * lane);
    const float rw2y = __ldg(W2 + 2 * lane + 1);
    const float bias2 = __ldg(b2);
    const int mode = g_mask_mode;
    __syncthreads();

    // Phase B thread decomposition: t = dq*64 + jgrp*4 + pgrp
    const int dq   = t >> 6;        // 0..7  -> d in [dq*16, dq*16+16)
    const int jgrp = (t >> 2) & 15; // j = jgrp*4 .. +3
    const int pgrp = t & 3;         // paths pgrp*4 .. +3

    for (int s = blockIdx.x; s < S; s += gridDim.x) {
        // ---------------- Phase A: gather (warp p <-> path p) --------------
        {
            const int p = warp;
            const int base = (s * PP + p) * KK;
            const int4* ip = (const int4*)(eids + base);

            unsigned mb = 0;
            if (mode == 0) {
                uint4 mv = __ldg((const uint4*)((const unsigned char*)maskp + base));
                unsigned wds[4] = {mv.x, mv.y, mv.z, mv.w};
                #pragma unroll
                for (int q = 0; q < 4; q++)
                    #pragma unroll
                    for (int b = 0; b < 4; b++)
                        mb |= (((wds[q] >> (8 * b)) & 0xFFu) ? 1u : 0u) << (q * 4 + b);
            } else if (mode == 1) {
                const int4* m4 = (const int4*)((const int*)maskp + base);
                #pragma unroll
                for (int q = 0; q < 4; q++) {
                    int4 mv = __ldg(m4 + q);
                    mb |= (mv.x ? 1u : 0u) << (q * 4 + 0);
                    mb |= (mv.y ? 1u : 0u) << (q * 4 + 1);
                    mb |= (mv.z ? 1u : 0u) << (q * 4 + 2);
                    mb |= (mv.w ? 1u : 0u) << (q * 4 + 3);
                }
            } else {
                const float4* m4 = (const float4*)((const float*)maskp + base);
                #pragma unroll
                for (int q = 0; q < 4; q++) {
                    float4 mv = __ldg(m4 + q);
                    mb |= (mv.x != 0.f ? 1u : 0u) << (q * 4 + 0);
                    mb |= (mv.y != 0.f ? 1u : 0u) << (q * 4 + 1);
                    mb |= (mv.z != 0.f ? 1u : 0u) << (q * 4 + 2);
                    mb |= (mv.w != 0.f ? 1u : 0u) << (q * 4 + 3);
                }
            }
            const int cnt = __popc(mb);

            const float4* E4 = (const float4*)E;
            float4 acc = make_float4(0.f, 0.f, 0.f, 0.f);
            // two chunks of 8 endpoints: keeps only 2 int4 of ids live
            #pragma unroll
            for (int h = 0; h < 2; h++) {
                int4 ia = __ldg(ip + 2 * h);
                int4 ib = __ldg(ip + 2 * h + 1);
                const int ids8[8] = {ia.x, ia.y, ia.z, ia.w, ib.x, ib.y, ib.z, ib.w};
                #pragma unroll
                for (int k = 0; k < 8; k++) {
                    if (mb & (1u << (8 * h + k))) {
                        float4 v = __ldg(E4 + ids8[k] * (DD / 4) + lane);
                        acc.x += v.x; acc.y += v.y; acc.z += v.z; acc.w += v.w;
                    }
                }
            }
            const float inv = 1.f / (float)(cnt > 0 ? cnt : 1);
            float4 a = make_float4(acc.x * inv, acc.y * inv, acc.z * inv, acc.w * inv);
            ((float4*)(sAgg + p * AGG_STRIDE))[lane] = a;
            if (lane == 0) sVal[p] = (cnt > 0);
        }
        __syncthreads();

        // -------- Phase B: tiled split-K GEMM h[p][j] partials --------------
        // thread: dq (16 d's), jgrp (4 j's = 1 ulonglong2), pgrp (4 paths)
        {
            const float* wp = sW1 + (dq * 16) * HH + jgrp * 4;
            const float* ap = sAgg + (pgrp * 4) * AGG_STRIDE + dq * 16;
            unsigned long long h0 = 0ull, h1 = 0ull, h2 = 0ull, h3 = 0ull;
            unsigned long long h4 = 0ull, h5 = 0ull, h6 = 0ull, h7 = 0ull;
            #pragma unroll
            for (int c = 0; c < 4; c++) {       // 4 chunks x 4 d's
                float4 a0 = *(const float4*)(ap + c * 4);
                float4 a1 = *(const float4*)(ap + AGG_STRIDE + c * 4);
                float4 a2 = *(const float4*)(ap + 2 * AGG_STRIDE + c * 4);
                float4 a3 = *(const float4*)(ap + 3 * AGG_STRIDE + c * 4);
                const float av0[4] = {a0.x, a0.y, a0.z, a0.w};
                const float av1[4] = {a1.x, a1.y, a1.z, a1.w};
                const float av2[4] = {a2.x, a2.y, a2.z, a2.w};
                const float av3[4] = {a3.x, a3.y, a3.z, a3.w};
                #pragma unroll
                for (int r = 0; r < 4; r++) {
                    ulonglong2 w = *(const ulonglong2*)(wp + (c * 4 + r) * HH);
                    unsigned long long aa;
                    aa = pack2(av0[r], av0[r]); fma2(h0, aa, w.x); fma2(h1, aa, w.y);
                    aa = pack2(av1[r], av1[r]); fma2(h2, aa, w.x); fma2(h3, aa, w.y);
                    aa = pack2(av2[r], av2[r]); fma2(h4, aa, w.x); fma2(h5, aa, w.y);
                    aa = pack2(av3[r], av3[r]); fma2(h6, aa, w.x); fma2(h7, aa, w.y);
                }
            }
            unsigned long long* pd = sPart + dq * PART_DQ + jgrp * 2;
            const int pb = pgrp * 4;
            pd[(pb + 0) * PART_PSTRIDE + 0] = h0;
            pd[(pb + 0) * PART_PSTRIDE + 1] = h1;
            pd[(pb + 1) * PART_PSTRIDE + 0] = h2;
            pd[(pb + 1) * PART_PSTRIDE + 1] = h3;
            pd[(pb + 2) * PART_PSTRIDE + 0] = h4;
            pd[(pb + 2) * PART_PSTRIDE + 1] = h5;
            pd[(pb + 3) * PART_PSTRIDE + 0] = h6;
            pd[(pb + 3) * PART_PSTRIDE + 1] = h7;
        }
        __syncthreads();

        // ------- Phase C: reduce split-K, bias+relu, dot W2, sigmoid -------
        // warp == path p; lane == j-pair index (j = 2*lane, 2*lane+1)
        {
            const int p = warp;
            float hx = 0.f, hy = 0.f;
            #pragma unroll
            for (int dqq = 0; dqq < 8; dqq++) {
                float2 v = unpack2(sPart[dqq * PART_DQ + p * PART_PSTRIDE + lane]);
                hx += v.x; hy += v.y;
            }
            float h0 = fmaxf(hx + rb1x, 0.f);
            float h1 = fmaxf(hy + rb1y, 0.f);
            float hw = h0 * rw2x + h1 * rw2y;
            #pragma unroll
            for (int o = 16; o; o >>= 1) hw += __shfl_xor_sync(0xffffffffu, hw, o);
            if (lane == 0) {
                float x = hw + bias2;
                float w = 1.f / (1.f + __expf(-x));
                sWgt[p] = sVal[p] ? w : 0.f;
            }
        }
        __syncthreads();

        // -------- Phase D: weighted mean over valid paths + scatter --------
        if (t < DD) {
            float o = 0.f;
            int nv = 0;
            #pragma unroll
            for (int p = 0; p < PP; p++) {
                o += sWgt[p] * sAgg[p * AGG_STRIDE + t];
                nv += sVal[p];
            }
            out[__ldg(sids + s) * DD + t] = o / (float)(nv > 0 ? nv : 1);
        }
        __syncthreads();
    }
}

extern "C" void kernel_launch(void* const* d_in, const int* in_sizes, int n_in,
                              void* d_out, int out_size) {
    const float* E   = (const float*)d_in[0];
    const float* W1  = (const float*)d_in[1];
    const float* b1  = (const float*)d_in[2];
    const float* W2  = (const float*)d_in[3];
    const float* b2  = (const float*)d_in[4];
    const int*   sid = (const int*)d_in[5];
    const int*   eid = (const int*)d_in[6];
    const void*  msk = d_in[7];
    float* out = (float*)d_out;

    const int S = in_sizes[5];

    cudaMemsetAsync(d_out, 0, (size_t)out_size * sizeof(float), 0);
    detect_mask_kernel<<<1, 1024>>>((const unsigned int*)msk);

    static const int SMEM_BYTES = SMEM_FLOATS * 4; // 75136 B
    cudaFuncSetAttribute(pga_kernel, cudaFuncAttributeMaxDynamicSharedMemorySize,
                         SMEM_BYTES);

    // 152 SMs x 3 blocks/SM = 456 persistent blocks.
    int grid = 456;
    if (grid > S) grid = S;
    pga_kernel<<<grid, 512, SMEM_BYTES>>>(E, W1, b1, W2, b2, sid, eid, msk, out, S);
}

// round 9
// speedup vs baseline: 1.0734x; 1.0734x over previous
#include <cuda_runtime.h>
#include <math.h>

// ---------------------------------------------------------------------------
// PathGuidedAggregator: S=8192 x P=16 x K=16, D=128, H=64
// Round 7: Phase-B retile (d16/j4/p4), warp==jgrp, lane=pgrp*8+dq.
// Split-K reduced by warp shuffles (sPart SMEM eliminated). W1 XOR-swizzled
// so each 8-lane phase group hits distinct bank quads. SMEM 43.1KB/block
// (R3: 58.2) -> L1D carveout 99KB (the R4/R6 regression was SMEM starving L1D
// to 2.6KB). Phase-B loads: 32 LDS.128/thread vs R3's 48.
// ---------------------------------------------------------------------------

#define DD 128
#define PP 16
#define KK 16
#define HH 64
#define AGG_STRIDE 132           // floats per sAgg row
#define SC_STRIDE 20             // floats per sC row (5p mod 8 distinct quads)

__device__ int g_mask_mode; // 0 = uint8, 1 = int32, 2 = float32

__global__ void detect_mask_kernel(const unsigned int* __restrict__ w) {
    __shared__ int f_gt1, f_one;
    if (threadIdx.x == 0) { f_gt1 = 0; f_one = 0; }
    __syncthreads();
    unsigned v = w[threadIdx.x];
    if (v == 0x3F800000u)      atomicOr(&f_one, 1);
    else if (v > 1u)           atomicOr(&f_gt1, 1);
    __syncthreads();
    if (threadIdx.x == 0)
        g_mask_mode = f_gt1 ? 0 : (f_one ? 2 : 1);
}

// ---- packed f32x2 helpers (sm_100+) ---------------------------------------
__device__ __forceinline__ unsigned long long pack2(float x, float y) {
    unsigned long long r;
    asm("mov.b64 %0, {%1, %2};" : "=l"(r) : "f"(x), "f"(y));
    return r;
}
__device__ __forceinline__ float2 unpack2(unsigned long long v) {
    float2 r;
    asm("mov.b64 {%0, %1}, %2;" : "=f"(r.x), "=f"(r.y) : "l"(v));
    return r;
}
__device__ __forceinline__ void fma2(unsigned long long& acc,
                                     unsigned long long a,
                                     unsigned long long b) {
    asm("fma.rn.f32x2 %0, %1, %2, %0;" : "+l"(acc) : "l"(a), "l"(b));
}
__device__ __forceinline__ unsigned long long add2(unsigned long long a,
                                                   unsigned long long b) {
    unsigned long long r;
    asm("add.rn.f32x2 %0, %1, %2;" : "=l"(r) : "l"(a), "l"(b));
    return r;
}

// Dynamic SMEM layout (float index):
//   sW1   [0     .. 8192)    32 KB  W1, rows 64 floats, XOR-swizzled quads
//   sAgg  [8192  .. 10304)   16 x 132
//   sC    [10304 .. 10624)   16 x 20 (per-path per-jgrp partial logits)
//   sWgt  [10624 .. 10640)
//   sVal  [10640 .. 10656)  (int)
//   sBW   [10656 .. 10784)   b1[64] then W2[64]
static const int SMEM_FLOATS = 10784;   // 43136 B

__global__ void __launch_bounds__(512, 3)
pga_kernel(const float* __restrict__ E, const float* __restrict__ W1,
           const float* __restrict__ b1, const float* __restrict__ W2,
           const float* __restrict__ b2, const int* __restrict__ sids,
           const int* __restrict__ eids, const void* __restrict__ maskp,
           float* __restrict__ out, int S) {
    extern __shared__ float smem[];
    float* sW1  = smem;
    float* sAgg = smem + 8192;
    float* sC   = smem + 10304;
    float* sWgt = smem + 10624;
    int*   sVal = (int*)(smem + 10640);
    float* sBW  = smem + 10656;

    const int t = threadIdx.x;
    const int lane = t & 31;
    const int warp = t >> 5;

    // W1 -> smem with XOR quad swizzle: float4 (r, cq) stored at
    // quad cq' = (cq & 8) | ((cq ^ (r>>2)) & 7)
    {
        const float4* w4 = (const float4*)W1;
        #pragma unroll
        for (int idx = t; idx < DD * HH / 4; idx += 512) {
            int r = idx >> 4, cq = idx & 15;
            int cqs = (cq & 8) | ((cq ^ (r >> 2)) & 7);
            ((float4*)sW1)[r * 16 + cqs] = __ldg(w4 + idx);
        }
    }
    // b1, W2 -> smem
    if (t < HH) { sBW[t] = __ldg(b1 + t); sBW[HH + t] = __ldg(W2 + t); }
    const float bias2 = __ldg(b2);
    const int mode = g_mask_mode;
    __syncthreads();

    // Phase B decomposition: warp == jgrp (j = jgrp*4..+3),
    // lane = pgrp*8 + dq:  pgrp -> paths pgrp*4..+3,  dq -> d-blocks dq+8i.
    const int jgrp = warp;
    const int pgrp = lane >> 3;
    const int dq   = lane & 7;
    // swizzled W1 column-quad for this thread (constant):
    const int swq = (jgrp & 8) | ((jgrp ^ dq) & 7);
    const float* wbase = sW1 + swq * 4;
    const float* abase = sAgg + (pgrp * 4) * AGG_STRIDE + dq * 4;

    for (int s = blockIdx.x; s < S; s += gridDim.x) {
        // ---------------- Phase A: gather (warp p <-> path p) --------------
        {
            const int p = warp;
            const int base = (s * PP + p) * KK;
            const int4* ip = (const int4*)(eids + base);

            unsigned mb = 0;
            if (mode == 0) {
                uint4 mv = __ldg((const uint4*)((const unsigned char*)maskp + base));
                unsigned wds[4] = {mv.x, mv.y, mv.z, mv.w};
                #pragma unroll
                for (int q = 0; q < 4; q++)
                    #pragma unroll
                    for (int b = 0; b < 4; b++)
                        mb |= (((wds[q] >> (8 * b)) & 0xFFu) ? 1u : 0u) << (q * 4 + b);
            } else if (mode == 1) {
                const int4* m4 = (const int4*)((const int*)maskp + base);
                #pragma unroll
                for (int q = 0; q < 4; q++) {
                    int4 mv = __ldg(m4 + q);
                    mb |= (mv.x ? 1u : 0u) << (q * 4 + 0);
                    mb |= (mv.y ? 1u : 0u) << (q * 4 + 1);
                    mb |= (mv.z ? 1u : 0u) << (q * 4 + 2);
                    mb |= (mv.w ? 1u : 0u) << (q * 4 + 3);
                }
            } else {
                const float4* m4 = (const float4*)((const float*)maskp + base);
                #pragma unroll
                for (int q = 0; q < 4; q++) {
                    float4 mv = __ldg(m4 + q);
                    mb |= (mv.x != 0.f ? 1u : 0u) << (q * 4 + 0);
                    mb |= (mv.y != 0.f ? 1u : 0u) << (q * 4 + 1);
                    mb |= (mv.z != 0.f ? 1u : 0u) << (q * 4 + 2);
                    mb |= (mv.w != 0.f ? 1u : 0u) << (q * 4 + 3);
                }
            }
            const int cnt = __popc(mb);

            const float4* E4 = (const float4*)E;
            float4 acc = make_float4(0.f, 0.f, 0.f, 0.f);
            #pragma unroll
            for (int h = 0; h < 2; h++) {
                int4 ia = __ldg(ip + 2 * h);
                int4 ib = __ldg(ip + 2 * h + 1);
                const int ids8[8] = {ia.x, ia.y, ia.z, ia.w, ib.x, ib.y, ib.z, ib.w};
                #pragma unroll
                for (int k = 0; k < 8; k++) {
                    if (mb & (1u << (8 * h + k))) {
                        float4 v = __ldg(E4 + ids8[k] * (DD / 4) + lane);
                        acc.x += v.x; acc.y += v.y; acc.z += v.z; acc.w += v.w;
                    }
                }
            }
            const float inv = 1.f / (float)(cnt > 0 ? cnt : 1);
            float4 a = make_float4(acc.x * inv, acc.y * inv, acc.z * inv, acc.w * inv);
            ((float4*)(sAgg + p * AGG_STRIDE))[lane] = a;
            if (lane == 0) sVal[p] = (cnt > 0);
        }
        __syncthreads();

        // ---- Phase B: GEMM partials, split-K over dq lanes -----------------
        {
            unsigned long long acc0x = 0ull, acc0y = 0ull, acc1x = 0ull, acc1y = 0ull;
            unsigned long long acc2x = 0ull, acc2y = 0ull, acc3x = 0ull, acc3y = 0ull;
            #pragma unroll 1
            for (int i = 0; i < 4; i++) {
                // agg: 4 paths x 4 d's (d-block dq + 8i)
                const float* ai = abase + 32 * i;
                float4 a0 = *(const float4*)(ai);
                float4 a1 = *(const float4*)(ai + AGG_STRIDE);
                float4 a2 = *(const float4*)(ai + 2 * AGG_STRIDE);
                float4 a3 = *(const float4*)(ai + 3 * AGG_STRIDE);
                const float av0[4] = {a0.x, a0.y, a0.z, a0.w};
                const float av1[4] = {a1.x, a1.y, a1.z, a1.w};
                const float av2[4] = {a2.x, a2.y, a2.z, a2.w};
                const float av3[4] = {a3.x, a3.y, a3.z, a3.w};
                const float* wrow = wbase + (4 * (dq + 8 * i)) * HH;
                #pragma unroll
                for (int rr = 0; rr < 4; rr++) {
                    ulonglong2 w = *(const ulonglong2*)(wrow + rr * HH);
                    unsigned long long aa;
                    aa = pack2(av0[rr], av0[rr]); fma2(acc0x, aa, w.x); fma2(acc0y, aa, w.y);
                    aa = pack2(av1[rr], av1[rr]); fma2(acc1x, aa, w.x); fma2(acc1y, aa, w.y);
                    aa = pack2(av2[rr], av2[rr]); fma2(acc2x, aa, w.x); fma2(acc2y, aa, w.y);
                    aa = pack2(av3[rr], av3[rr]); fma2(acc3x, aa, w.x); fma2(acc3y, aa, w.y);
                }
            }
            // butterfly reduce over dq (lane bits 0-2)
            #pragma unroll
            for (int m = 1; m <= 4; m <<= 1) {
                acc0x = add2(acc0x, __shfl_xor_sync(0xffffffffu, acc0x, m));
                acc0y = add2(acc0y, __shfl_xor_sync(0xffffffffu, acc0y, m));
                acc1x = add2(acc1x, __shfl_xor_sync(0xffffffffu, acc1x, m));
                acc1y = add2(acc1y, __shfl_xor_sync(0xffffffffu, acc1y, m));
                acc2x = add2(acc2x, __shfl_xor_sync(0xffffffffu, acc2x, m));
                acc2y = add2(acc2y, __shfl_xor_sync(0xffffffffu, acc2y, m));
                acc3x = add2(acc3x, __shfl_xor_sync(0xffffffffu, acc3x, m));
                acc3y = add2(acc3y, __shfl_xor_sync(0xffffffffu, acc3y, m));
            }
            // epilogue: lanes dq==0 compute per-path partial logit for 4 j's
            if (dq == 0) {
                const int j0 = jgrp * 4;
                const float b1v0 = sBW[j0],      b1v1 = sBW[j0 + 1];
                const float b1v2 = sBW[j0 + 2],  b1v3 = sBW[j0 + 3];
                const float w2v0 = sBW[HH + j0],     w2v1 = sBW[HH + j0 + 1];
                const float w2v2 = sBW[HH + j0 + 2], w2v3 = sBW[HH + j0 + 3];
                unsigned long long hx[4] = {acc0x, acc1x, acc2x, acc3x};
                unsigned long long hy[4] = {acc0y, acc1y, acc2y, acc3y};
                #pragma unroll
                for (int k = 0; k < 4; k++) {
                    float2 u = unpack2(hx[k]);
                    float2 v = unpack2(hy[k]);
                    float pw = fmaxf(u.x + b1v0, 0.f) * w2v0
                             + fmaxf(u.y + b1v1, 0.f) * w2v1
                             + fmaxf(v.x + b1v2, 0.f) * w2v2
                             + fmaxf(v.y + b1v3, 0.f) * w2v3;
                    sC[(pgrp * 4 + k) * SC_STRIDE + jgrp] = pw;
                }
            }
        }
        __syncthreads();

        // ---- Phase C2: sum partial logits over jgrp, sigmoid --------------
        if (t < PP) {
            const float* cr = sC + t * SC_STRIDE;
            float4 c0 = *(const float4*)(cr);
            float4 c1 = *(const float4*)(cr + 4);
            float4 c2 = *(const float4*)(cr + 8);
            float4 c3 = *(const float4*)(cr + 12);
            float x = (((c0.x + c0.y) + (c0.z + c0.w)) + ((c1.x + c1.y) + (c1.z + c1.w)))
                    + (((c2.x + c2.y) + (c2.z + c2.w)) + ((c3.x + c3.y) + (c3.z + c3.w)))
                    + bias2;
            float w = 1.f / (1.f + __expf(-x));
            sWgt[t] = sVal[t] ? w : 0.f;
        }
        __syncthreads();

        // -------- Phase D: weighted mean over valid paths + scatter --------
        if (t < DD) {
            float o = 0.f;
            int nv = 0;
            #pragma unroll
            for (int p = 0; p < PP; p++) {
                o += sWgt[p] * sAgg[p * AGG_STRIDE + t];
                nv += sVal[p];
            }
            out[__ldg(sids + s) * DD + t] = o / (float)(nv > 0 ? nv : 1);
        }
        __syncthreads();
    }
}

extern "C" void kernel_launch(void* const* d_in, const int* in_sizes, int n_in,
                              void* d_out, int out_size) {
    const float* E   = (const float*)d_in[0];
    const float* W1  = (const float*)d_in[1];
    const float* b1  = (const float*)d_in[2];
    const float* W2  = (const float*)d_in[3];
    const float* b2  = (const float*)d_in[4];
    const int*   sid = (const int*)d_in[5];
    const int*   eid = (const int*)d_in[6];
    const void*  msk = d_in[7];
    float* out = (float*)d_out;

    const int S = in_sizes[5];

    cudaMemsetAsync(d_out, 0, (size_t)out_size * sizeof(float), 0);
    detect_mask_kernel<<<1, 1024>>>((const unsigned int*)msk);

    static const int SMEM_BYTES = SMEM_FLOATS * 4; // 43136 B
    cudaFuncSetAttribute(pga_kernel, cudaFuncAttributeMaxDynamicSharedMemorySize,
                         SMEM_BYTES);

    // 152 SMs x 3 blocks/SM = 456 persistent blocks.
    int grid = 456;
    if (grid > S) grid = S;
    pga_kernel<<<grid, 512, SMEM_BYTES>>>(E, W1, b1, W2, b2, sid, eid, msk, out, S);
}

// round 10
// speedup vs baseline: 1.2723x; 1.1852x over previous
#include <cuda_runtime.h>
#include <math.h>

// ---------------------------------------------------------------------------
// PathGuidedAggregator: S=8192 x P=16 x K=16, D=128, H=64
// Round 8: R3 (best, 144.8us) + double-buffered sAgg/sVal/sWgt so the
// end-of-node __syncthreads is removed (4 -> 3 syncs/node). Phase D (4 warps)
// now overlaps the next node's gather; gather imbalance partially absorbed.
// Phase-B tiling is R3's exact (2p x 4j x 32d) — retilings R4/R6/R7 all lost.
// ---------------------------------------------------------------------------

#define DD 128
#define PP 16
#define KK 16
#define HH 64
#define AGG_STRIDE 132           // floats per sAgg row
#define PART_PSTRIDE 33          // ull per path row in sPart
#define PART_DQ (16 * PART_PSTRIDE)  // 528 ull per d-quarter

__device__ int g_mask_mode; // 0 = uint8, 1 = int32, 2 = float32

__global__ void detect_mask_kernel(const unsigned int* __restrict__ w) {
    __shared__ int f_gt1, f_one;
    if (threadIdx.x == 0) { f_gt1 = 0; f_one = 0; }
    __syncthreads();
    unsigned v = w[threadIdx.x];
    if (v == 0x3F800000u)      atomicOr(&f_one, 1);
    else if (v > 1u)           atomicOr(&f_gt1, 1);
    __syncthreads();
    if (threadIdx.x == 0)
        g_mask_mode = f_gt1 ? 0 : (f_one ? 2 : 1);
}

// ---- packed f32x2 helpers (sm_100+) ---------------------------------------
__device__ __forceinline__ unsigned long long pack2(float x, float y) {
    unsigned long long r;
    asm("mov.b64 %0, {%1, %2};" : "=l"(r) : "f"(x), "f"(y));
    return r;
}
__device__ __forceinline__ float2 unpack2(unsigned long long v) {
    float2 r;
    asm("mov.b64 {%0, %1}, %2;" : "=f"(r.x), "=f"(r.y) : "l"(v));
    return r;
}
__device__ __forceinline__ void fma2(unsigned long long& acc,
                                     unsigned long long a,
                                     unsigned long long b) {
    asm("fma.rn.f32x2 %0, %1, %2, %0;" : "+l"(acc) : "l"(a), "l"(b));
}

// Dynamic SMEM layout (float index):
//   sW1    [0     .. 8192)    32 KB  W1[d][j] row-major
//   sAgg0  [8192  .. 10304)   16 x 132
//   sAgg1  [10304 .. 12416)   16 x 132
//   sPart  [12416 .. 16640)   4 dq x 528 ull (16.9 KB)
//   sWgt   [16640 .. 16672)   2 x 16
//   sVal   [16672 .. 16704)   2 x 16 (int)
static const int SMEM_FLOATS = 16704;   // 66816 B

__global__ void __launch_bounds__(512, 3)
pga_kernel(const float* __restrict__ E, const float* __restrict__ W1,
           const float* __restrict__ b1, const float* __restrict__ W2,
           const float* __restrict__ b2, const int* __restrict__ sids,
           const int* __restrict__ eids, const void* __restrict__ maskp,
           float* __restrict__ out, int S) {
    extern __shared__ float smem[];
    float* sW1  = smem;
    unsigned long long* sPart = (unsigned long long*)(smem + 12416);

    const int t = threadIdx.x;
    const int lane = t & 31;
    const int warp = t >> 5;

    // W1 -> smem (vectorized)
    {
        const float4* w4 = (const float4*)W1;
        #pragma unroll
        for (int i = t; i < DD * HH / 4; i += 512)
            ((float4*)sW1)[i] = __ldg(w4 + i);
    }
    // Phase C per-thread constants (indexed by lane only)
    const float rb1x = __ldg(b1 + 2 * lane);
    const float rb1y = __ldg(b1 + 2 * lane + 1);
    const float rw2x = __ldg(W2 + 2 * lane);
    const float rw2y = __ldg(W2 + 2 * lane + 1);
    const float bias2 = __ldg(b2);
    const int mode = g_mask_mode;
    __syncthreads();

    // Phase B thread decomposition (R3): t = dq*128 + jgrp*8 + pgrp
    const int dq   = t >> 7;        // 0..3  -> d in [dq*32, dq*32+32)
    const int jgrp = (t >> 3) & 15; // j = jgrp*4 .. +3
    const int pgrp = t & 7;         // paths pgrp and pgrp+8

    int buf = 0;
    for (int s = blockIdx.x; s < S; s += gridDim.x, buf ^= 1) {
        float* sAgg = smem + 8192 + buf * (PP * AGG_STRIDE);
        float* sWgt = smem + 16640 + buf * PP;
        int*   sVal = (int*)(smem + 16672) + buf * PP;

        // ---------------- Phase A: gather (warp p <-> path p) --------------
        {
            const int p = warp;
            const int base = (s * PP + p) * KK;
            const int4* ip = (const int4*)(eids + base);

            unsigned mb = 0;
            if (mode == 0) {
                uint4 mv = __ldg((const uint4*)((const unsigned char*)maskp + base));
                unsigned wds[4] = {mv.x, mv.y, mv.z, mv.w};
                #pragma unroll
                for (int q = 0; q < 4; q++)
                    #pragma unroll
                    for (int b = 0; b < 4; b++)
                        mb |= (((wds[q] >> (8 * b)) & 0xFFu) ? 1u : 0u) << (q * 4 + b);
            } else if (mode == 1) {
                const int4* m4 = (const int4*)((const int*)maskp + base);
                #pragma unroll
                for (int q = 0; q < 4; q++) {
                    int4 mv = __ldg(m4 + q);
                    mb |= (mv.x ? 1u : 0u) << (q * 4 + 0);
                    mb |= (mv.y ? 1u : 0u) << (q * 4 + 1);
                    mb |= (mv.z ? 1u : 0u) << (q * 4 + 2);
                    mb |= (mv.w ? 1u : 0u) << (q * 4 + 3);
                }
            } else {
                const float4* m4 = (const float4*)((const float*)maskp + base);
                #pragma unroll
                for (int q = 0; q < 4; q++) {
                    float4 mv = __ldg(m4 + q);
                    mb |= (mv.x != 0.f ? 1u : 0u) << (q * 4 + 0);
                    mb |= (mv.y != 0.f ? 1u : 0u) << (q * 4 + 1);
                    mb |= (mv.z != 0.f ? 1u : 0u) << (q * 4 + 2);
                    mb |= (mv.w != 0.f ? 1u : 0u) << (q * 4 + 3);
                }
            }
            const int cnt = __popc(mb);

            const float4* E4 = (const float4*)E;
            float4 acc = make_float4(0.f, 0.f, 0.f, 0.f);
            #pragma unroll
            for (int h = 0; h < 2; h++) {
                int4 ia = __ldg(ip + 2 * h);
                int4 ib = __ldg(ip + 2 * h + 1);
                const int ids8[8] = {ia.x, ia.y, ia.z, ia.w, ib.x, ib.y, ib.z, ib.w};
                #pragma unroll
                for (int k = 0; k < 8; k++) {
                    if (mb & (1u << (8 * h + k))) {
                        float4 v = __ldg(E4 + ids8[k] * (DD / 4) + lane);
                        acc.x += v.x; acc.y += v.y; acc.z += v.z; acc.w += v.w;
                    }
                }
            }
            const float inv = 1.f / (float)(cnt > 0 ? cnt : 1);
            float4 a = make_float4(acc.x * inv, acc.y * inv, acc.z * inv, acc.w * inv);
            ((float4*)(sAgg + p * AGG_STRIDE))[lane] = a;
            if (lane == 0) sVal[p] = (cnt > 0);
        }
        __syncthreads();   // S1: sAgg(buf) ready

        // -------- Phase B: tiled split-K GEMM h[p][j] partials (R3) ---------
        {
            const float* a0p = sAgg + pgrp * AGG_STRIDE + dq * 32;
            const float* a1p = a0p + 8 * AGG_STRIDE;
            const float* wp  = sW1 + (dq * 32) * HH + jgrp * 4;
            unsigned long long acc00 = 0ull, acc01 = 0ull;
            unsigned long long acc10 = 0ull, acc11 = 0ull;
            #pragma unroll
            for (int step = 0; step < 8; step++) {
                float4 a0 = *(const float4*)(a0p + step * 4);
                float4 a1 = *(const float4*)(a1p + step * 4);
                float av0[4] = {a0.x, a0.y, a0.z, a0.w};
                float av1[4] = {a1.x, a1.y, a1.z, a1.w};
                #pragma unroll
                for (int r = 0; r < 4; r++) {
                    ulonglong2 w = *(const ulonglong2*)(wp + (step * 4 + r) * HH);
                    unsigned long long aa0 = pack2(av0[r], av0[r]);
                    unsigned long long aa1 = pack2(av1[r], av1[r]);
                    fma2(acc00, aa0, w.x); fma2(acc01, aa0, w.y);
                    fma2(acc10, aa1, w.x); fma2(acc11, aa1, w.y);
                }
            }
            unsigned long long* pd = sPart + dq * PART_DQ;
            pd[pgrp       * PART_PSTRIDE + jgrp * 2 + 0] = acc00;
            pd[pgrp       * PART_PSTRIDE + jgrp * 2 + 1] = acc01;
            pd[(pgrp + 8) * PART_PSTRIDE + jgrp * 2 + 0] = acc10;
            pd[(pgrp + 8) * PART_PSTRIDE + jgrp * 2 + 1] = acc11;
        }
        __syncthreads();   // S2: sPart ready

        // ------- Phase C: reduce split-K, bias+relu, dot W2, sigmoid -------
        {
            const int p = warp;
            float hx = 0.f, hy = 0.f;
            #pragma unroll
            for (int dqq = 0; dqq < 4; dqq++) {
                float2 v = unpack2(sPart[dqq * PART_DQ + p * PART_PSTRIDE + lane]);
                hx += v.x; hy += v.y;
            }
            float h0 = fmaxf(hx + rb1x, 0.f);
            float h1 = fmaxf(hy + rb1y, 0.f);
            float hw = h0 * rw2x + h1 * rw2y;
            #pragma unroll
            for (int o = 16; o; o >>= 1) hw += __shfl_xor_sync(0xffffffffu, hw, o);
            if (lane == 0) {
                float x = hw + bias2;
                float w = 1.f / (1.f + __expf(-x));
                sWgt[p] = sVal[p] ? w : 0.f;
            }
        }
        __syncthreads();   // S3: sWgt ready

        // -------- Phase D: weighted mean + scatter (overlaps next gather) ---
        if (t < DD) {
            float o = 0.f;
            int nv = 0;
            #pragma unroll
            for (int p = 0; p < PP; p++) {
                o += sWgt[p] * sAgg[p * AGG_STRIDE + t];
                nv += sVal[p];
            }
            out[__ldg(sids + s) * DD + t] = o / (float)(nv > 0 ? nv : 1);
        }
        // no end-of-node sync: buffers are double-buffered; D overlaps the
        // next node's Phase A. sPart reuse is fenced by S1(next)+S2(next).
    }
}

extern "C" void kernel_launch(void* const* d_in, const int* in_sizes, int n_in,
                              void* d_out, int out_size) {
    const float* E   = (const float*)d_in[0];
    const float* W1  = (const float*)d_in[1];
    const float* b1  = (const float*)d_in[2];
    const float* W2  = (const float*)d_in[3];
    const float* b2  = (const float*)d_in[4];
    const int*   sid = (const int*)d_in[5];
    const int*   eid = (const int*)d_in[6];
    const void*  msk = d_in[7];
    float* out = (float*)d_out;

    const int S = in_sizes[5];

    cudaMemsetAsync(d_out, 0, (size_t)out_size * sizeof(float), 0);
    detect_mask_kernel<<<1, 1024>>>((const unsigned int*)msk);

    static const int SMEM_BYTES = SMEM_FLOATS * 4; // 66816 B
    cudaFuncSetAttribute(pga_kernel, cudaFuncAttributeMaxDynamicSharedMemorySize,
                         SMEM_BYTES);

    // 152 SMs x 3 blocks/SM = 456 persistent blocks.
    int grid = 456;
    if (grid > S) grid = S;
    pga_kernel<<<grid, 512, SMEM_BYTES>>>(E, W1, b1, W2, b2, sid, eid, msk, out, S);
}

// round 11
// speedup vs baseline: 1.3249x; 1.0414x over previous
#include <cuda_runtime.h>
#include <math.h>

// ---------------------------------------------------------------------------
// PathGuidedAggregator: S=8192 x P=16 x K=16, D=128, H=64
// Round 9: single-kernel graph. R8 core (best) +
//  - inline per-block mask dtype detection (detect kernel removed)
//  - output zeroing folded into the kernel, overlapped with first gather via
//    a soft grid barrier (grid=456 == exactly-resident 3/SM x 152 SM)
//  - prefetch.global.L1 of next node's ids+mask lines
// Phase-B tiling frozen at R3 shape (Pareto floor under the 42-reg cap).
// ---------------------------------------------------------------------------

#define DD 128
#define PP 16
#define KK 16
#define HH 64
#define AGG_STRIDE 132           // floats per sAgg row
#define PART_PSTRIDE 33          // ull per path row in sPart
#define PART_DQ (16 * PART_PSTRIDE)  // 528 ull per d-quarter

__device__ int g_zero_done = 0;   // blocks that finished zeroing
__device__ int g_exit_cnt  = 0;   // blocks that finished the kernel

// ---- packed f32x2 helpers (sm_100+) ---------------------------------------
__device__ __forceinline__ unsigned long long pack2(float x, float y) {
    unsigned long long r;
    asm("mov.b64 %0, {%1, %2};" : "=l"(r) : "f"(x), "f"(y));
    return r;
}
__device__ __forceinline__ float2 unpack2(unsigned long long v) {
    float2 r;
    asm("mov.b64 {%0, %1}, %2;" : "=f"(r.x), "=f"(r.y) : "l"(v));
    return r;
}
__device__ __forceinline__ void fma2(unsigned long long& acc,
                                     unsigned long long a,
                                     unsigned long long b) {
    asm("fma.rn.f32x2 %0, %1, %2, %0;" : "+l"(acc) : "l"(a), "l"(b));
}

// Dynamic SMEM layout (float index):
//   sW1    [0     .. 8192)    32 KB  W1[d][j] row-major
//   sAgg0  [8192  .. 10304)   16 x 132
//   sAgg1  [10304 .. 12416)   16 x 132
//   sPart  [12416 .. 16640)   4 dq x 528 ull (16.9 KB)
//   sWgt   [16640 .. 16672)   2 x 16
//   sVal   [16672 .. 16704)   2 x 16 (int)
static const int SMEM_FLOATS = 16704;   // 66816 B

__global__ void __launch_bounds__(512, 3)
pga_kernel(const float* __restrict__ E, const float* __restrict__ W1,
           const float* __restrict__ b1, const float* __restrict__ W2,
           const float* __restrict__ b2, const int* __restrict__ sids,
           const int* __restrict__ eids, const void* __restrict__ maskp,
           float* __restrict__ out, int S, int out_n) {
    extern __shared__ float smem[];
    float* sW1  = smem;
    unsigned long long* sPart = (unsigned long long*)(smem + 12416);

    const int t = threadIdx.x;
    const int lane = t & 31;
    const int warp = t >> 5;
    const int grid = gridDim.x;

    // ---- Zero phase: grid-stride float4 zero of the output ---------------
    {
        float4 z = make_float4(0.f, 0.f, 0.f, 0.f);
        const int n4 = out_n >> 2;
        for (int i = blockIdx.x * 512 + t; i < n4; i += grid * 512)
            ((float4*)out)[i] = z;
        for (int i = (n4 << 2) + blockIdx.x * 512 + t; i < out_n; i += grid * 512)
            out[i] = 0.f;
        __syncthreads();          // all block's zero STGs issued
        if (t == 0) {
            __threadfence();
            atomicAdd(&g_zero_done, 1);
        }
    }

    // ---- Inline mask dtype detection (same 1024 words, all blocks agree) --
    int mode;
    {
        const unsigned* mw = (const unsigned*)maskp;
        unsigned v0 = __ldg(mw + t), v1 = __ldg(mw + 512 + t);
        int gt1 = ((v0 > 1u) && (v0 != 0x3F800000u)) ||
                  ((v1 > 1u) && (v1 != 0x3F800000u));
        int one = (v0 == 0x3F800000u) || (v1 == 0x3F800000u);
        int any_gt1 = __syncthreads_or(gt1);
        int any_one = __syncthreads_or(one);
        mode = any_gt1 ? 0 : (any_one ? 2 : 1);
    }

    // W1 -> smem (vectorized)
    {
        const float4* w4 = (const float4*)W1;
        #pragma unroll
        for (int i = t; i < DD * HH / 4; i += 512)
            ((float4*)sW1)[i] = __ldg(w4 + i);
    }
    // Phase C per-thread constants (indexed by lane only)
    const float rb1x = __ldg(b1 + 2 * lane);
    const float rb1y = __ldg(b1 + 2 * lane + 1);
    const float rw2x = __ldg(W2 + 2 * lane);
    const float rw2y = __ldg(W2 + 2 * lane + 1);
    const float bias2 = __ldg(b2);
    __syncthreads();

    // Phase B thread decomposition (R3): t = dq*128 + jgrp*8 + pgrp
    const int dq   = t >> 7;        // 0..3  -> d in [dq*32, dq*32+32)
    const int jgrp = (t >> 3) & 15; // j = jgrp*4 .. +3
    const int pgrp = t & 7;         // paths pgrp and pgrp+8

    bool first = true;
    int buf = 0;
    for (int s = blockIdx.x; s < S; s += grid, buf ^= 1) {
        float* sAgg = smem + 8192 + buf * (PP * AGG_STRIDE);
        float* sWgt = smem + 16640 + buf * PP;
        int*   sVal = (int*)(smem + 16672) + buf * PP;

        // ---------------- Phase A: gather (warp p <-> path p) --------------
        {
            const int p = warp;
            const int base = (s * PP + p) * KK;
            const int4* ip = (const int4*)(eids + base);

            // prefetch next node's id + mask lines (lane 0 only)
            if (lane == 0 && s + grid < S) {
                const int nb = ((s + grid) * PP + p) * KK;
                asm volatile("prefetch.global.L1 [%0];" :: "l"(eids + nb));
                const char* mpc = (const char*)maskp +
                                  ((mode == 0) ? (size_t)nb : (size_t)nb * 4);
                asm volatile("prefetch.global.L1 [%0];" :: "l"(mpc));
            }

            unsigned mb = 0;
            if (mode == 0) {
                uint4 mv = __ldg((const uint4*)((const unsigned char*)maskp + base));
                unsigned wds[4] = {mv.x, mv.y, mv.z, mv.w};
                #pragma unroll
                for (int q = 0; q < 4; q++)
                    #pragma unroll
                    for (int b = 0; b < 4; b++)
                        mb |= (((wds[q] >> (8 * b)) & 0xFFu) ? 1u : 0u) << (q * 4 + b);
            } else if (mode == 1) {
                const int4* m4 = (const int4*)((const int*)maskp + base);
                #pragma unroll
                for (int q = 0; q < 4; q++) {
                    int4 mv = __ldg(m4 + q);
                    mb |= (mv.x ? 1u : 0u) << (q * 4 + 0);
                    mb |= (mv.y ? 1u : 0u) << (q * 4 + 1);
                    mb |= (mv.z ? 1u : 0u) << (q * 4 + 2);
                    mb |= (mv.w ? 1u : 0u) << (q * 4 + 3);
                }
            } else {
                const float4* m4 = (const float4*)((const float*)maskp + base);
                #pragma unroll
                for (int q = 0; q < 4; q++) {
                    float4 mv = __ldg(m4 + q);
                    mb |= (mv.x != 0.f ? 1u : 0u) << (q * 4 + 0);
                    mb |= (mv.y != 0.f ? 1u : 0u) << (q * 4 + 1);
                    mb |= (mv.z != 0.f ? 1u : 0u) << (q * 4 + 2);
                    mb |= (mv.w != 0.f ? 1u : 0u) << (q * 4 + 3);
                }
            }
            const int cnt = __popc(mb);

            const float4* E4 = (const float4*)E;
            float4 acc = make_float4(0.f, 0.f, 0.f, 0.f);
            #pragma unroll
            for (int h = 0; h < 2; h++) {
                int4 ia = __ldg(ip + 2 * h);
                int4 ib = __ldg(ip + 2 * h + 1);
                const int ids8[8] = {ia.x, ia.y, ia.z, ia.w, ib.x, ib.y, ib.z, ib.w};
                #pragma unroll
                for (int k = 0; k < 8; k++) {
                    if (mb & (1u << (8 * h + k))) {
                        float4 v = __ldg(E4 + ids8[k] * (DD / 4) + lane);
                        acc.x += v.x; acc.y += v.y; acc.z += v.z; acc.w += v.w;
                    }
                }
            }
            const float inv = 1.f / (float)(cnt > 0 ? cnt : 1);
            float4 a = make_float4(acc.x * inv, acc.y * inv, acc.z * inv, acc.w * inv);
            ((float4*)(sAgg + p * AGG_STRIDE))[lane] = a;
            if (lane == 0) sVal[p] = (cnt > 0);
        }
        __syncthreads();   // S1: sAgg(buf) ready

        // -------- Phase B: tiled split-K GEMM h[p][j] partials (R3) ---------
        {
            const float* a0p = sAgg + pgrp * AGG_STRIDE + dq * 32;
            const float* a1p = a0p + 8 * AGG_STRIDE;
            const float* wp  = sW1 + (dq * 32) * HH + jgrp * 4;
            unsigned long long acc00 = 0ull, acc01 = 0ull;
            unsigned long long acc10 = 0ull, acc11 = 0ull;
            #pragma unroll
            for (int step = 0; step < 8; step++) {
                float4 a0 = *(const float4*)(a0p + step * 4);
                float4 a1 = *(const float4*)(a1p + step * 4);
                float av0[4] = {a0.x, a0.y, a0.z, a0.w};
                float av1[4] = {a1.x, a1.y, a1.z, a1.w};
                #pragma unroll
                for (int r = 0; r < 4; r++) {
                    ulonglong2 w = *(const ulonglong2*)(wp + (step * 4 + r) * HH);
                    unsigned long long aa0 = pack2(av0[r], av0[r]);
                    unsigned long long aa1 = pack2(av1[r], av1[r]);
                    fma2(acc00, aa0, w.x); fma2(acc01, aa0, w.y);
                    fma2(acc10, aa1, w.x); fma2(acc11, aa1, w.y);
                }
            }
            unsigned long long* pd = sPart + dq * PART_DQ;
            pd[pgrp       * PART_PSTRIDE + jgrp * 2 + 0] = acc00;
            pd[pgrp       * PART_PSTRIDE + jgrp * 2 + 1] = acc01;
            pd[(pgrp + 8) * PART_PSTRIDE + jgrp * 2 + 0] = acc10;
            pd[(pgrp + 8) * PART_PSTRIDE + jgrp * 2 + 1] = acc11;
        }
        __syncthreads();   // S2: sPart ready

        // ------- Phase C: reduce split-K, bias+relu, dot W2, sigmoid -------
        {
            const int p = warp;
            float hx = 0.f, hy = 0.f;
            #pragma unroll
            for (int dqq = 0; dqq < 4; dqq++) {
                float2 v = unpack2(sPart[dqq * PART_DQ + p * PART_PSTRIDE + lane]);
                hx += v.x; hy += v.y;
            }
            float h0 = fmaxf(hx + rb1x, 0.f);
            float h1 = fmaxf(hy + rb1y, 0.f);
            float hw = h0 * rw2x + h1 * rw2y;
            #pragma unroll
            for (int o = 16; o; o >>= 1) hw += __shfl_xor_sync(0xffffffffu, hw, o);
            if (lane == 0) {
                float x = hw + bias2;
                float w = 1.f / (1.f + __expf(-x));
                sWgt[p] = sVal[p] ? w : 0.f;
            }
        }
        __syncthreads();   // S3: sWgt ready

        // ---- soft grid barrier before the FIRST output write only --------
        if (first) {
            if (t == 0) {
                while (atomicAdd(&g_zero_done, 0) < grid) { }
            }
            __syncthreads();
            first = false;
        }

        // -------- Phase D: weighted mean + scatter (overlaps next gather) ---
        if (t < DD) {
            float o = 0.f;
            int nv = 0;
            #pragma unroll
            for (int p = 0; p < PP; p++) {
                o += sWgt[p] * sAgg[p * AGG_STRIDE + t];
                nv += sVal[p];
            }
            out[__ldg(sids + s) * DD + t] = o / (float)(nv > 0 ? nv : 1);
        }
        // no end-of-node sync (double-buffered; sPart fenced by S1+S2 next).
    }

    // ---- reset counters for deterministic graph replay --------------------
    __syncthreads();
    if (t == 0) {
        __threadfence();
        int d = atomicAdd(&g_exit_cnt, 1);
        if (d == grid - 1) {
            g_zero_done = 0;
            g_exit_cnt  = 0;
        }
    }
}

extern "C" void kernel_launch(void* const* d_in, const int* in_sizes, int n_in,
                              void* d_out, int out_size) {
    const float* E   = (const float*)d_in[0];
    const float* W1  = (const float*)d_in[1];
    const float* b1  = (const float*)d_in[2];
    const float* W2  = (const float*)d_in[3];
    const float* b2  = (const float*)d_in[4];
    const int*   sid = (const int*)d_in[5];
    const int*   eid = (const int*)d_in[6];
    const void*  msk = d_in[7];
    float* out = (float*)d_out;

    const int S = in_sizes[5];

    static const int SMEM_BYTES = SMEM_FLOATS * 4; // 66816 B
    cudaFuncSetAttribute(pga_kernel, cudaFuncAttributeMaxDynamicSharedMemorySize,
                         SMEM_BYTES);

    // 152 SMs x 3 blocks/SM = 456 blocks — exactly co-resident, which makes
    // the in-kernel soft grid barrier deadlock-free.
    int grid = 456;
    pga_kernel<<<grid, 512, SMEM_BYTES>>>(E, W1, b1, W2, b2, sid, eid, msk,
                                          out, S, out_size);
}